// round 9
// baseline (speedup 1.0000x reference)
#include <cuda_runtime.h>
#include <cuda_bf16.h>
#include <cstdint>
#include <cstddef>

#define TT 8192
#define DD 2048
#define EE 8
#define NROWS 9216
#define MAX_MTILES 72

#define MT 128           /* CTA tile M */
#define NT 256           /* CTA tile N */
#define KC 32            /* K per chunk (row = 64 bytes bf16) */
#define STAGES 6
#define CHUNKS 192       /* 3*2048/32 */
#define A_BYTES (MT*KC*2)             /* 8192  */
#define B_BYTES (NT*KC*2)             /* 16384 */
#define STAGE_BYTES (A_BYTES+B_BYTES) /* 24576 */
#define SMEM_NEED (STAGES*STAGE_BYTES)/* 147456 */

// ---------------- device scratch ----------------
__device__ __nv_bfloat16 g_xh[(size_t)NROWS*DD];
__device__ __nv_bfloat16 g_xl[(size_t)NROWS*DD];
__device__ __nv_bfloat16 g_Wh[(size_t)EE*DD*DD];
__device__ __nv_bfloat16 g_Wl[(size_t)EE*DD*DD];
__device__ int   g_expert[TT];
__device__ float g_topp[TT];
__device__ int   g_row2tok[NROWS];
__device__ int   g_cnt[EE];
__device__ int   g_cursor[EE];
__device__ int   g_off[EE];
__device__ float g_tpsum[EE];
__device__ int   g_tile_expert[MAX_MTILES];
__device__ int   g_num_tiles;

// ---------------- helpers ----------------
__device__ __forceinline__ uint32_t smem_u32(const void* p) {
    uint32_t a;
    asm("{ .reg .u64 t; cvta.to.shared.u64 t, %1; cvt.u32.u64 %0, t; }" : "=r"(a) : "l"(p));
    return a;
}
__device__ __forceinline__ void cp_async16(uint32_t dst, const void* src) {
    asm volatile("cp.async.cg.shared.global [%0], [%1], 16;" :: "r"(dst), "l"(src) : "memory");
}
__device__ __forceinline__ uint32_t pack_bf2(__nv_bfloat16 a, __nv_bfloat16 b) {
    return (uint32_t)__bfloat16_as_ushort(a) | ((uint32_t)__bfloat16_as_ushort(b) << 16);
}
// split a float4 into bf16 hi (rn) + bf16 lo (residual), packed as 2x uint2
__device__ __forceinline__ void split4(float4 v, uint2& hh, uint2& ll) {
    __nv_bfloat16 h0 = __float2bfloat16(v.x), h1 = __float2bfloat16(v.y);
    __nv_bfloat16 h2 = __float2bfloat16(v.z), h3 = __float2bfloat16(v.w);
    __nv_bfloat16 l0 = __float2bfloat16(v.x - __bfloat162float(h0));
    __nv_bfloat16 l1 = __float2bfloat16(v.y - __bfloat162float(h1));
    __nv_bfloat16 l2 = __float2bfloat16(v.z - __bfloat162float(h2));
    __nv_bfloat16 l3 = __float2bfloat16(v.w - __bfloat162float(h3));
    hh.x = pack_bf2(h0, h1); hh.y = pack_bf2(h2, h3);
    ll.x = pack_bf2(l0, l1); ll.y = pack_bf2(l2, l3);
}
__device__ __forceinline__ void ldsm_x4(uint32_t& r0, uint32_t& r1, uint32_t& r2, uint32_t& r3,
                                        uint32_t addr) {
    asm volatile("ldmatrix.sync.aligned.m8n8.x4.shared.b16 {%0,%1,%2,%3}, [%4];"
                 : "=r"(r0), "=r"(r1), "=r"(r2), "=r"(r3) : "r"(addr));
}
__device__ __forceinline__ void mma_bf16(float* c, const uint32_t* a, const uint32_t* b) {
    asm volatile(
        "mma.sync.aligned.m16n8k16.row.col.f32.bf16.bf16.f32 "
        "{%0,%1,%2,%3}, {%4,%5,%6,%7}, {%8,%9}, {%0,%1,%2,%3};"
        : "+f"(c[0]), "+f"(c[1]), "+f"(c[2]), "+f"(c[3])
        : "r"(a[0]), "r"(a[1]), "r"(a[2]), "r"(a[3]), "r"(b[0]), "r"(b[1]));
}

// ---------------- small kernels ----------------
__global__ void k_reset() {
    int i = blockIdx.x * 256 + threadIdx.x;
    if (i < NROWS) g_row2tok[i] = -1;
    if (blockIdx.x == 0 && threadIdx.x < EE) {
        g_cnt[threadIdx.x] = 0; g_cursor[threadIdx.x] = 0; g_tpsum[threadIdx.x] = 0.f;
    }
}

__global__ void k_convw(const float4* __restrict__ W) {
    size_t i = (size_t)blockIdx.x * blockDim.x + threadIdx.x;   // EE*DD*DD/4 threads
    uint2 hh, ll;
    split4(W[i], hh, ll);
    ((uint2*)g_Wh)[i] = hh;
    ((uint2*)g_Wl)[i] = ll;
}

__global__ void k_router(const float* __restrict__ x, const float* __restrict__ Wr,
                         const float* __restrict__ br) {
    int t = blockIdx.x * 8 + (threadIdx.x >> 5);
    int lid = threadIdx.x & 31;
    const float4* xr = (const float4*)(x + (size_t)t * DD);
    const float4* wr = (const float4*)Wr;
    float acc[EE];
#pragma unroll
    for (int e = 0; e < EE; e++) acc[e] = 0.f;
    for (int i = lid; i < DD / 4; i += 32) {
        float4 xv = xr[i];
#pragma unroll
        for (int e = 0; e < EE; e++) {
            float4 w = wr[e * (DD / 4) + i];
            acc[e] += xv.x * w.x + xv.y * w.y + xv.z * w.z + xv.w * w.w;
        }
    }
#pragma unroll
    for (int e = 0; e < EE; e++)
#pragma unroll
        for (int o = 16; o; o >>= 1) acc[e] += __shfl_xor_sync(0xffffffffu, acc[e], o);
    if (lid == 0) {
        float mx = -1e30f; int idx = 0;
#pragma unroll
        for (int e = 0; e < EE; e++) {
            acc[e] += br[e];
            if (acc[e] > mx) { mx = acc[e]; idx = e; }
        }
        float s = 0.f;
#pragma unroll
        for (int e = 0; e < EE; e++) s += expf(acc[e] - mx);
        float tp = 1.f / s;
        g_expert[t] = idx; g_topp[t] = tp;
        atomicAdd(&g_cnt[idx], 1);
        atomicAdd(&g_tpsum[idx], tp);
    }
}

__global__ void k_schedule(float* __restrict__ out, int out_size) {
    if (threadIdx.x == 0) {
        int off = 0, nt = 0;
        float loss = 0.f;
        for (int e = 0; e < EE; e++) {
            g_off[e] = off;
            int c = g_cnt[e];
            int tiles = (c + MT - 1) / MT;
            for (int i = 0; i < tiles; i++) g_tile_expert[nt + i] = e;
            nt += tiles; off += tiles * MT;
            float frac = (float)c / (float)TT;
            float prob = g_tpsum[e] / ((float)TT * (float)TT);
            loss += frac * prob;
        }
        g_num_tiles = nt;
        loss *= 3e-06f * (float)EE;
        if (out_size == TT * DD + 1) out[(size_t)TT * DD] = loss;
    }
}

__global__ void k_gather(const float* __restrict__ x) {
    __shared__ int s_row;
    int t = blockIdx.x;
    if (threadIdx.x == 0) {
        int e = g_expert[t];
        int r = g_off[e] + atomicAdd(&g_cursor[e], 1);
        g_row2tok[r] = t;
        s_row = r;
    }
    __syncthreads();
    int r = s_row;
    const float4* src = (const float4*)(x + (size_t)t * DD);
    uint2* dh = (uint2*)(g_xh + (size_t)r * DD);
    uint2* dl = (uint2*)(g_xl + (size_t)r * DD);
    for (int i = threadIdx.x; i < DD / 4; i += 256) {
        uint2 hh, ll;
        split4(src[i], hh, ll);
        dh[i] = hh; dl[i] = ll;
    }
}

__global__ void k_padzero() {
    int r = blockIdx.x;
    if (g_row2tok[r] >= 0) return;
    uint4 z = make_uint4(0, 0, 0, 0);
    uint4* a = (uint4*)(g_xh + (size_t)r * DD);
    uint4* b = (uint4*)(g_xl + (size_t)r * DD);
    a[threadIdx.x] = z; b[threadIdx.x] = z;   // 256 threads x 16B = 4KB row
}

// ---------------- GEMM (HMMA mma.sync, 128x256 CTA tile, warp tile 64x64) ----------------
__global__ void __launch_bounds__(256, 1)
k_gemm(const float* __restrict__ bias, float* __restrict__ out) {
    int mtile = blockIdx.y, ntile = blockIdx.x;
    if (mtile >= g_num_tiles) return;
    int e = g_tile_expert[mtile];

    extern __shared__ char smem[];
    uint32_t tiles0 = smem_u32(smem);

    int tid = threadIdx.x, wid = tid >> 5, lane = tid & 31;
    int wm = wid >> 2, wn = wid & 3;         // 2 x 4 warp grid, warp tile 64x64

    const __nv_bfloat16* Bh = g_Wh + ((size_t)e * DD + (size_t)ntile * NT) * DD;
    const __nv_bfloat16* Bl = g_Wl + ((size_t)e * DD + (size_t)ntile * NT) * DD;
    size_t arow0 = (size_t)mtile * MT * DD;

    // loader mapping: row = tid>>2 (+64/+128/+192), 16B piece = tid&3
    int lr0 = tid >> 2, lc = tid & 3;

    auto load_chunk = [&](int c, int slot) {
        int seg = c >> 6;                 // 0: xh*Wh  1: xh*Wl  2: xl*Wh
        int kc = (c & 63) * KC;
        const __nv_bfloat16* Asrc = (seg < 2 ? g_xh : g_xl) + arow0 + kc;
        const __nv_bfloat16* Bsrc = (seg == 1 ? Bl : Bh) + kc;
        uint32_t abase = tiles0 + slot * STAGE_BYTES;
        uint32_t bbase = abase + A_BYTES;
#pragma unroll
        for (int p = 0; p < 2; p++) {     // A: 128 rows
            int r = lr0 + p * 64;
            uint32_t soff = (uint32_t)r * 64u + (uint32_t)((lc ^ ((r >> 1) & 3)) << 4);
            cp_async16(abase + soff, (const char*)(Asrc + (size_t)r * DD) + lc * 16);
        }
#pragma unroll
        for (int p = 0; p < 4; p++) {     // B: 256 rows
            int r = lr0 + p * 64;
            uint32_t soff = (uint32_t)r * 64u + (uint32_t)((lc ^ ((r >> 1) & 3)) << 4);
            cp_async16(bbase + soff, (const char*)(Bsrc + (size_t)r * DD) + lc * 16);
        }
        asm volatile("cp.async.commit_group;" ::: "memory");
    };

    // ldmatrix address components (constant over chunks)
    int khA = (lane >> 4) & 1;               // A: k-half from lane bit4
    int khB = (lane >> 3) & 1;               // B: k-half from lane bit3
    uint32_t aob[4]; int asw[4];
#pragma unroll
    for (int mf = 0; mf < 4; mf++) {
        int r = wm * 64 + mf * 16 + (lane & 7) + 8 * ((lane >> 3) & 1);
        aob[mf] = (uint32_t)r * 64u;
        asw[mf] = (r >> 1) & 3;
    }
    uint32_t bob[4]; int bsw[4];
#pragma unroll
    for (int p = 0; p < 4; p++) {
        int n = wn * 64 + p * 16 + (lane & 7) + 8 * ((lane >> 4) & 1);
        bob[p] = (uint32_t)n * 64u;
        bsw[p] = (n >> 1) & 3;
    }

    float acc[4][8][4];
#pragma unroll
    for (int i = 0; i < 4; i++)
#pragma unroll
        for (int j = 0; j < 8; j++)
#pragma unroll
            for (int q = 0; q < 4; q++) acc[i][j][q] = 0.f;

    // prologue: stages 0..4
    for (int c = 0; c < STAGES - 1; c++) load_chunk(c, c);

    int slot = 0;
    for (int c = 0; c < CHUNKS; c++) {
        asm volatile("cp.async.wait_group %0;" :: "n"(STAGES - 2) : "memory");
        __syncthreads();
        int nl = c + STAGES - 1;
        int nslot = slot + STAGES - 1; if (nslot >= STAGES) nslot -= STAGES;
        if (nl < CHUNKS) load_chunk(nl, nslot);
        else asm volatile("cp.async.commit_group;" ::: "memory");

        uint32_t as = tiles0 + slot * STAGE_BYTES;
        uint32_t bs = as + A_BYTES;
#pragma unroll
        for (int ks = 0; ks < 2; ks++) {
            uint32_t aR[4][4], bR[8][2];
#pragma unroll
            for (int mf = 0; mf < 4; mf++)
                ldsm_x4(aR[mf][0], aR[mf][1], aR[mf][2], aR[mf][3],
                        as + aob[mf] + (uint32_t)(((ks * 2 + khA) ^ asw[mf]) << 4));
#pragma unroll
            for (int p = 0; p < 4; p++)
                ldsm_x4(bR[2 * p][0], bR[2 * p][1], bR[2 * p + 1][0], bR[2 * p + 1][1],
                        bs + bob[p] + (uint32_t)(((ks * 2 + khB) ^ bsw[p]) << 4));
#pragma unroll
            for (int mf = 0; mf < 4; mf++)
#pragma unroll
                for (int nf = 0; nf < 8; nf++)
                    mma_bf16(acc[mf][nf], aR[mf], bR[nf]);
        }
        __syncthreads();
        if (++slot == STAGES) slot = 0;
    }

    // epilogue: (acc + bias) * topp, scatter rows to tokens
    int g = lane >> 2, tq = lane & 3;
    const float* brow = bias + (size_t)e * DD + (size_t)ntile * NT;
#pragma unroll
    for (int mf = 0; mf < 4; mf++) {
#pragma unroll
        for (int half = 0; half < 2; half++) {
            int m = mtile * MT + wm * 64 + mf * 16 + g + half * 8;
            int tok = g_row2tok[m];
            if (tok < 0) continue;
            float tp = g_topp[tok];
            float* orow = out + (size_t)tok * DD + (size_t)ntile * NT;
#pragma unroll
            for (int nf = 0; nf < 8; nf++) {
                int n = wn * 64 + nf * 8 + 2 * tq;
                float2 o;
                o.x = (acc[mf][nf][half * 2 + 0] + brow[n]) * tp;
                o.y = (acc[mf][nf][half * 2 + 1] + brow[n + 1]) * tp;
                *(float2*)(orow + n) = o;
            }
        }
    }
}

// ---------------- launcher ----------------
extern "C" void kernel_launch(void* const* d_in, const int* in_sizes, int n_in,
                              void* d_out, int out_size) {
    const float* x  = (const float*)d_in[0];
    const float* Wr = (const float*)d_in[1];
    const float* br = (const float*)d_in[2];
    const float* W  = (const float*)d_in[3];
    const float* b  = (const float*)d_in[4];
    float* out = (float*)d_out;

    cudaFuncSetAttribute(k_gemm, cudaFuncAttributeMaxDynamicSharedMemorySize, SMEM_NEED);

    k_reset<<<(NROWS + 255) / 256, 256>>>();
    k_convw<<<(int)((size_t)EE * DD * DD / 4 / 256), 256>>>((const float4*)W);
    k_router<<<TT / 8, 256>>>(x, Wr, br);
    k_schedule<<<1, 32>>>(out, out_size);
    k_gather<<<TT, 256>>>(x);
    k_padzero<<<NROWS, 256>>>();
    k_gemm<<<dim3(DD / NT, MAX_MTILES), 256, SMEM_NEED>>>(b, out);
}

// round 10
// speedup vs baseline: 2.6717x; 2.6717x over previous
#include <cuda_runtime.h>
#include <cuda_fp16.h>
#include <cstdint>
#include <cstddef>

#define TT 8192
#define DD 2048
#define EE 8
#define NROWS 9216
#define MAX_MTILES 72

#define MT 128           /* CTA tile M */
#define NT 128           /* CTA tile N */
#define KC 64            /* K per chunk (row = 128 bytes fp16) */
#define STAGES 3
#define CHUNKS (DD/KC)   /* 32 */
#define A_BYTES (MT*KC*2)             /* 16384 */
#define B_BYTES (NT*KC*2)             /* 16384 */
#define STAGE_BYTES (A_BYTES+B_BYTES) /* 32768 */
#define SMEM_NEED (STAGES*STAGE_BYTES)/* 98304 */

// ---------------- device scratch ----------------
__device__ __align__(16) __half g_xf[(size_t)NROWS*DD];
__device__ __align__(16) __half g_Wf[(size_t)EE*DD*DD];
__device__ int   g_expert[TT];
__device__ float g_topp[TT];
__device__ int   g_row2tok[NROWS];
__device__ int   g_cnt[EE];
__device__ int   g_cursor[EE];
__device__ int   g_off[EE];
__device__ float g_tpsum[EE];
__device__ int   g_tile_expert[MAX_MTILES];
__device__ int   g_num_tiles;

// ---------------- helpers ----------------
__device__ __forceinline__ uint32_t smem_u32(const void* p) {
    uint32_t a;
    asm("{ .reg .u64 t; cvta.to.shared.u64 t, %1; cvt.u32.u64 %0, t; }" : "=r"(a) : "l"(p));
    return a;
}
__device__ __forceinline__ void cp_async16(uint32_t dst, const void* src) {
    asm volatile("cp.async.cg.shared.global [%0], [%1], 16;" :: "r"(dst), "l"(src) : "memory");
}
__device__ __forceinline__ uint2 cvt4_h(float4 v) {
    __half2 a = __floats2half2_rn(v.x, v.y);
    __half2 b = __floats2half2_rn(v.z, v.w);
    uint2 r;
    r.x = *(uint32_t*)&a; r.y = *(uint32_t*)&b;
    return r;
}
__device__ __forceinline__ void ldsm_x4(uint32_t& r0, uint32_t& r1, uint32_t& r2, uint32_t& r3,
                                        uint32_t addr) {
    asm volatile("ldmatrix.sync.aligned.m8n8.x4.shared.b16 {%0,%1,%2,%3}, [%4];"
                 : "=r"(r0), "=r"(r1), "=r"(r2), "=r"(r3) : "r"(addr));
}
__device__ __forceinline__ void mma_f16(float* c, const uint32_t* a, const uint32_t* b) {
    asm volatile(
        "mma.sync.aligned.m16n8k16.row.col.f32.f16.f16.f32 "
        "{%0,%1,%2,%3}, {%4,%5,%6,%7}, {%8,%9}, {%0,%1,%2,%3};"
        : "+f"(c[0]), "+f"(c[1]), "+f"(c[2]), "+f"(c[3])
        : "r"(a[0]), "r"(a[1]), "r"(a[2]), "r"(a[3]), "r"(b[0]), "r"(b[1]));
}

// ---------------- small kernels ----------------
__global__ void k_reset() {
    int i = blockIdx.x * 256 + threadIdx.x;
    if (i < NROWS) g_row2tok[i] = -1;
    if (blockIdx.x == 0 && threadIdx.x < EE) {
        g_cnt[threadIdx.x] = 0; g_cursor[threadIdx.x] = 0; g_tpsum[threadIdx.x] = 0.f;
    }
}

__global__ void k_convw(const float4* __restrict__ W) {
    size_t i = (size_t)blockIdx.x * blockDim.x + threadIdx.x;   // EE*DD*DD/4 threads
    ((uint2*)g_Wf)[i] = cvt4_h(W[i]);
}

__global__ void k_router(const float* __restrict__ x, const float* __restrict__ Wr,
                         const float* __restrict__ br) {
    int t = blockIdx.x * 8 + (threadIdx.x >> 5);
    int lid = threadIdx.x & 31;
    const float4* xr = (const float4*)(x + (size_t)t * DD);
    const float4* wr = (const float4*)Wr;
    float acc[EE];
#pragma unroll
    for (int e = 0; e < EE; e++) acc[e] = 0.f;
    for (int i = lid; i < DD / 4; i += 32) {
        float4 xv = xr[i];
#pragma unroll
        for (int e = 0; e < EE; e++) {
            float4 w = wr[e * (DD / 4) + i];
            acc[e] += xv.x * w.x + xv.y * w.y + xv.z * w.z + xv.w * w.w;
        }
    }
#pragma unroll
    for (int e = 0; e < EE; e++)
#pragma unroll
        for (int o = 16; o; o >>= 1) acc[e] += __shfl_xor_sync(0xffffffffu, acc[e], o);
    if (lid == 0) {
        float mx = -1e30f; int idx = 0;
#pragma unroll
        for (int e = 0; e < EE; e++) {
            acc[e] += br[e];
            if (acc[e] > mx) { mx = acc[e]; idx = e; }
        }
        float s = 0.f;
#pragma unroll
        for (int e = 0; e < EE; e++) s += expf(acc[e] - mx);
        float tp = 1.f / s;
        g_expert[t] = idx; g_topp[t] = tp;
        atomicAdd(&g_cnt[idx], 1);
        atomicAdd(&g_tpsum[idx], tp);
    }
}

__global__ void k_schedule(float* __restrict__ out, int out_size) {
    if (threadIdx.x == 0) {
        int off = 0, nt = 0;
        float loss = 0.f;
        for (int e = 0; e < EE; e++) {
            g_off[e] = off;
            int c = g_cnt[e];
            int tiles = (c + MT - 1) / MT;
            for (int i = 0; i < tiles; i++) g_tile_expert[nt + i] = e;
            nt += tiles; off += tiles * MT;
            float frac = (float)c / (float)TT;
            float prob = g_tpsum[e] / ((float)TT * (float)TT);
            loss += frac * prob;
        }
        g_num_tiles = nt;
        loss *= 3e-06f * (float)EE;
        if (out_size == TT * DD + 1) out[(size_t)TT * DD] = loss;
    }
}

__global__ void k_gather(const float* __restrict__ x) {
    __shared__ int s_row;
    int t = blockIdx.x;
    if (threadIdx.x == 0) {
        int e = g_expert[t];
        int r = g_off[e] + atomicAdd(&g_cursor[e], 1);
        g_row2tok[r] = t;
        s_row = r;
    }
    __syncthreads();
    int r = s_row;
    const float4* src = (const float4*)(x + (size_t)t * DD);
    uint2* dst = (uint2*)(g_xf + (size_t)r * DD);
    for (int i = threadIdx.x; i < DD / 4; i += 256) dst[i] = cvt4_h(src[i]);
}

__global__ void k_padzero() {
    int r = blockIdx.x;
    if (g_row2tok[r] >= 0) return;
    uint4 z = make_uint4(0, 0, 0, 0);
    ((uint4*)(g_xf + (size_t)r * DD))[threadIdx.x] = z;   // 256 x 16B = 4KB row
}

// ---------------- GEMM (HMMA fp16, 128x128 CTA tile, warp 64x32, occ 2) ----------------
__global__ void __launch_bounds__(256, 2)
k_gemm(const float* __restrict__ bias, float* __restrict__ out) {
    int mtile = blockIdx.y, ntile = blockIdx.x;
    if (mtile >= g_num_tiles) return;
    int e = g_tile_expert[mtile];

    extern __shared__ char smem[];
    uint32_t tiles0 = smem_u32(smem);

    int tid = threadIdx.x, wid = tid >> 5, lane = tid & 31;
    int wm = wid >> 2, wn = wid & 3;         // 2 x 4 warp grid, warp tile 64x32

    const __half* Bsrc0 = g_Wf + ((size_t)e * DD + (size_t)ntile * NT) * DD;
    const __half* Asrc0 = g_xf + (size_t)mtile * MT * DD;

    // loader: 8 threads per 128B row, 4 row-passes
    int lrow = tid >> 3, lp = tid & 7;

    auto load_chunk = [&](int c, int slot) {
        int kc = c * KC;
        uint32_t abase = tiles0 + slot * STAGE_BYTES;
        uint32_t bbase = abase + A_BYTES;
        const char* Ag = (const char*)(Asrc0 + kc) + lp * 16;
        const char* Bg = (const char*)(Bsrc0 + kc) + lp * 16;
#pragma unroll
        for (int p = 0; p < 4; p++) {
            int r = lrow + p * 32;
            uint32_t soff = (uint32_t)r * 128u + (uint32_t)((lp ^ (r & 7)) << 4);
            cp_async16(abase + soff, Ag + (size_t)r * (DD * 2));
            cp_async16(bbase + soff, Bg + (size_t)r * (DD * 2));
        }
        asm volatile("cp.async.commit_group;" ::: "memory");
    };

    // ldmatrix address components (constant over chunks)
    int khA = (lane >> 4) & 1;               // A: k-half from lane bit4
    int khB = (lane >> 3) & 1;               // B: k-half from lane bit3
    uint32_t aob[4]; int asw[4];
#pragma unroll
    for (int mf = 0; mf < 4; mf++) {
        int r = wm * 64 + mf * 16 + (lane & 7) + 8 * ((lane >> 3) & 1);
        aob[mf] = (uint32_t)r * 128u;
        asw[mf] = r & 7;
    }
    uint32_t bob[2]; int bsw[2];
#pragma unroll
    for (int p = 0; p < 2; p++) {
        int n = wn * 32 + p * 16 + (lane & 7) + 8 * ((lane >> 4) & 1);
        bob[p] = (uint32_t)n * 128u;
        bsw[p] = n & 7;
    }

    float acc[4][4][4];
#pragma unroll
    for (int i = 0; i < 4; i++)
#pragma unroll
        for (int j = 0; j < 4; j++)
#pragma unroll
            for (int q = 0; q < 4; q++) acc[i][j][q] = 0.f;

    // prologue: stages 0,1
    load_chunk(0, 0);
    load_chunk(1, 1);

    int slot = 0;
    for (int c = 0; c < CHUNKS; c++) {
        asm volatile("cp.async.wait_group 1;" ::: "memory");
        __syncthreads();
        int nslot = slot + 2; if (nslot >= STAGES) nslot -= STAGES;
        if (c + 2 < CHUNKS) load_chunk(c + 2, nslot);
        else asm volatile("cp.async.commit_group;" ::: "memory");

        uint32_t as = tiles0 + slot * STAGE_BYTES;
        uint32_t bs = as + A_BYTES;
#pragma unroll
        for (int ks = 0; ks < 4; ks++) {
            uint32_t aR[4][4], bR[4][2];
#pragma unroll
            for (int mf = 0; mf < 4; mf++)
                ldsm_x4(aR[mf][0], aR[mf][1], aR[mf][2], aR[mf][3],
                        as + aob[mf] + (uint32_t)(((ks * 2 + khA) ^ asw[mf]) << 4));
#pragma unroll
            for (int p = 0; p < 2; p++)
                ldsm_x4(bR[2 * p][0], bR[2 * p][1], bR[2 * p + 1][0], bR[2 * p + 1][1],
                        bs + bob[p] + (uint32_t)(((ks * 2 + khB) ^ bsw[p]) << 4));
#pragma unroll
            for (int mf = 0; mf < 4; mf++)
#pragma unroll
                for (int nf = 0; nf < 4; nf++)
                    mma_f16(acc[mf][nf], aR[mf], bR[nf]);
        }
        if (++slot == STAGES) slot = 0;
    }

    // epilogue: (acc + bias) * topp, scatter rows to tokens
    int g = lane >> 2, tq = lane & 3;
    const float* brow = bias + (size_t)e * DD + (size_t)ntile * NT;
#pragma unroll
    for (int mf = 0; mf < 4; mf++) {
#pragma unroll
        for (int half = 0; half < 2; half++) {
            int m = mtile * MT + wm * 64 + mf * 16 + g + half * 8;
            int tok = g_row2tok[m];
            if (tok < 0) continue;
            float tp = g_topp[tok];
            float* orow = out + (size_t)tok * DD + (size_t)ntile * NT;
#pragma unroll
            for (int nf = 0; nf < 4; nf++) {
                int n = wn * 32 + nf * 8 + 2 * tq;
                float2 o;
                o.x = (acc[mf][nf][half * 2 + 0] + brow[n]) * tp;
                o.y = (acc[mf][nf][half * 2 + 1] + brow[n + 1]) * tp;
                *(float2*)(orow + n) = o;
            }
        }
    }
}

// ---------------- launcher ----------------
extern "C" void kernel_launch(void* const* d_in, const int* in_sizes, int n_in,
                              void* d_out, int out_size) {
    const float* x  = (const float*)d_in[0];
    const float* Wr = (const float*)d_in[1];
    const float* br = (const float*)d_in[2];
    const float* W  = (const float*)d_in[3];
    const float* b  = (const float*)d_in[4];
    float* out = (float*)d_out;

    cudaFuncSetAttribute(k_gemm, cudaFuncAttributeMaxDynamicSharedMemorySize, SMEM_NEED);

    k_reset<<<(NROWS + 255) / 256, 256>>>();
    k_convw<<<(int)((size_t)EE * DD * DD / 4 / 256), 256>>>((const float4*)W);
    k_router<<<TT / 8, 256>>>(x, Wr, br);
    k_schedule<<<1, 32>>>(out, out_size);
    k_gather<<<TT, 256>>>(x);
    k_padzero<<<NROWS, 256>>>();
    k_gemm<<<dim3(DD / NT, MAX_MTILES), 256, SMEM_NEED>>>(b, out);
}

// round 11
// speedup vs baseline: 2.9068x; 1.0880x over previous
#include <cuda_runtime.h>
#include <cuda_fp16.h>
#include <cstdint>
#include <cstddef>

#define TT 8192
#define DD 2048
#define EE 8
#define NROWS 9216
#define MAX_MTILES 72

#define MT 128           /* CTA tile M */
#define NT 128           /* CTA tile N */
#define KC 64            /* K per chunk (row = 128 bytes fp16) */
#define STAGES 3
#define CHUNKS (DD/KC)   /* 32 */
#define A_BYTES (MT*KC*2)             /* 16384 */
#define B_BYTES (NT*KC*2)             /* 16384 */
#define STAGE_BYTES (A_BYTES+B_BYTES) /* 32768 */
#define SMEM_NEED (STAGES*STAGE_BYTES)/* 98304 */

// ---------------- device scratch ----------------
__device__ __align__(16) __half g_xf[(size_t)TT*DD];     /* token-ordered fp16 x */
__device__ __align__(16) __half g_Wf[(size_t)EE*DD*DD];  /* fp16 W */
__device__ int   g_expert[TT];
__device__ float g_topp[TT];
__device__ int   g_row2tok[NROWS];
__device__ int   g_cnt[EE];
__device__ int   g_cursor[EE];
__device__ int   g_off[EE];
__device__ float g_tpsum[EE];
__device__ int   g_tile_expert[MAX_MTILES];
__device__ int   g_num_tiles;

// ---------------- helpers ----------------
__device__ __forceinline__ uint32_t smem_u32(const void* p) {
    uint32_t a;
    asm("{ .reg .u64 t; cvta.to.shared.u64 t, %1; cvt.u32.u64 %0, t; }" : "=r"(a) : "l"(p));
    return a;
}
__device__ __forceinline__ void cp_async16(uint32_t dst, const void* src) {
    asm volatile("cp.async.cg.shared.global [%0], [%1], 16;" :: "r"(dst), "l"(src) : "memory");
}
// cp.async with runtime src-size (0 => full zero-fill of the 16B)
__device__ __forceinline__ void cp_async16z(uint32_t dst, const void* src, uint32_t srcsz) {
    asm volatile("cp.async.cg.shared.global [%0], [%1], 16, %2;"
                 :: "r"(dst), "l"(src), "r"(srcsz) : "memory");
}
__device__ __forceinline__ uint2 cvt4_h(float4 v) {
    __half2 a = __floats2half2_rn(v.x, v.y);
    __half2 b = __floats2half2_rn(v.z, v.w);
    uint2 r;
    r.x = *(uint32_t*)&a; r.y = *(uint32_t*)&b;
    return r;
}
__device__ __forceinline__ void ldsm_x4(uint32_t& r0, uint32_t& r1, uint32_t& r2, uint32_t& r3,
                                        uint32_t addr) {
    asm volatile("ldmatrix.sync.aligned.m8n8.x4.shared.b16 {%0,%1,%2,%3}, [%4];"
                 : "=r"(r0), "=r"(r1), "=r"(r2), "=r"(r3) : "r"(addr));
}
__device__ __forceinline__ void mma_f16(float* c, const uint32_t* a, const uint32_t* b) {
    asm volatile(
        "mma.sync.aligned.m16n8k16.row.col.f32.f16.f16.f32 "
        "{%0,%1,%2,%3}, {%4,%5,%6,%7}, {%8,%9}, {%0,%1,%2,%3};"
        : "+f"(c[0]), "+f"(c[1]), "+f"(c[2]), "+f"(c[3])
        : "r"(a[0]), "r"(a[1]), "r"(a[2]), "r"(a[3]), "r"(b[0]), "r"(b[1]));
}

// ---------------- small kernels ----------------
__global__ void k_reset() {
    int i = blockIdx.x * 256 + threadIdx.x;
    if (i < NROWS) g_row2tok[i] = -1;
    if (blockIdx.x == 0 && threadIdx.x < EE) {
        g_cnt[threadIdx.x] = 0; g_cursor[threadIdx.x] = 0; g_tpsum[threadIdx.x] = 0.f;
    }
}

__global__ void k_convw(const float4* __restrict__ W) {
    size_t i = (size_t)blockIdx.x * blockDim.x + threadIdx.x;   // EE*DD*DD/4 threads
    ((uint2*)g_Wf)[i] = cvt4_h(W[i]);
}

// router + inline fp16 conversion of x (token order)
__global__ void k_router(const float* __restrict__ x, const float* __restrict__ Wr,
                         const float* __restrict__ br) {
    int t = blockIdx.x * 8 + (threadIdx.x >> 5);
    int lid = threadIdx.x & 31;
    const float4* xr = (const float4*)(x + (size_t)t * DD);
    const float4* wr = (const float4*)Wr;
    uint2* xo = (uint2*)(g_xf + (size_t)t * DD);
    float acc[EE];
#pragma unroll
    for (int e = 0; e < EE; e++) acc[e] = 0.f;
    for (int i = lid; i < DD / 4; i += 32) {
        float4 xv = xr[i];
        xo[i] = cvt4_h(xv);
#pragma unroll
        for (int e = 0; e < EE; e++) {
            float4 w = wr[e * (DD / 4) + i];
            acc[e] += xv.x * w.x + xv.y * w.y + xv.z * w.z + xv.w * w.w;
        }
    }
#pragma unroll
    for (int e = 0; e < EE; e++)
#pragma unroll
        for (int o = 16; o; o >>= 1) acc[e] += __shfl_xor_sync(0xffffffffu, acc[e], o);
    if (lid == 0) {
        float mx = -1e30f; int idx = 0;
#pragma unroll
        for (int e = 0; e < EE; e++) {
            acc[e] += br[e];
            if (acc[e] > mx) { mx = acc[e]; idx = e; }
        }
        float s = 0.f;
#pragma unroll
        for (int e = 0; e < EE; e++) s += expf(acc[e] - mx);
        float tp = 1.f / s;
        g_expert[t] = idx; g_topp[t] = tp;
        atomicAdd(&g_cnt[idx], 1);
        atomicAdd(&g_tpsum[idx], tp);
    }
}

__global__ void k_schedule(float* __restrict__ out, int out_size) {
    if (threadIdx.x == 0) {
        int off = 0, nt = 0;
        float loss = 0.f;
        for (int e = 0; e < EE; e++) {
            g_off[e] = off;
            int c = g_cnt[e];
            int tiles = (c + MT - 1) / MT;
            for (int i = 0; i < tiles; i++) g_tile_expert[nt + i] = e;
            nt += tiles; off += tiles * MT;
            float frac = (float)c / (float)TT;
            float prob = g_tpsum[e] / ((float)TT * (float)TT);
            loss += frac * prob;
        }
        g_num_tiles = nt;
        loss *= 3e-06f * (float)EE;
        if (out_size == TT * DD + 1) out[(size_t)TT * DD] = loss;
    }
}

__global__ void k_fillmap() {
    int t = blockIdx.x * 256 + threadIdx.x;
    if (t >= TT) return;
    int e = g_expert[t];
    int r = g_off[e] + atomicAdd(&g_cursor[e], 1);
    g_row2tok[r] = t;
}

// ---------------- GEMM (HMMA fp16, 128x128 CTA, 4 warps, warp tile 64x64, occ 2) -------
__global__ void __launch_bounds__(128, 2)
k_gemm(const float* __restrict__ bias, float* __restrict__ out) {
    int mtile = blockIdx.y, ntile = blockIdx.x;
    if (mtile >= g_num_tiles) return;
    int e = g_tile_expert[mtile];

    extern __shared__ char smem[];
    uint32_t tiles0 = smem_u32(smem);

    int tid = threadIdx.x, wid = tid >> 5, lane = tid & 31;
    int wm = wid >> 1, wn = wid & 1;          // 2 x 2 warp grid, warp tile 64x64

    const __half* Bsrc0 = g_Wf + ((size_t)e * DD + (size_t)ntile * NT) * DD;

    // loader: 8 threads per 128B row, 8 row-passes (rows lrow + p*16)
    int lrow = tid >> 3, lp = tid & 7;
    const char* Bg = (const char*)Bsrc0 + lp * 16;

    // indirect A row pointers (gather through row2tok, zero-fill pads)
    const char* aptr[8];
    uint32_t asz[8];
#pragma unroll
    for (int p = 0; p < 8; p++) {
        int tok = g_row2tok[mtile * MT + lrow + p * 16];
        asz[p] = (tok >= 0) ? 16u : 0u;
        aptr[p] = (const char*)(g_xf + (size_t)(tok < 0 ? 0 : tok) * DD) + lp * 16;
    }

    auto load_chunk = [&](int c, int slot) {
        uint32_t abase = tiles0 + slot * STAGE_BYTES;
        uint32_t bbase = abase + A_BYTES;
        size_t coff = (size_t)c * (KC * 2);
#pragma unroll
        for (int p = 0; p < 8; p++) {
            int r = lrow + p * 16;
            uint32_t soff = (uint32_t)r * 128u + (uint32_t)((lp ^ (r & 7)) << 4);
            cp_async16z(abase + soff, aptr[p] + coff, asz[p]);
            cp_async16(bbase + soff, Bg + coff + (size_t)r * (DD * 2));
        }
        asm volatile("cp.async.commit_group;" ::: "memory");
    };

    // ldmatrix address components (constant over chunks)
    int khA = (lane >> 4) & 1;
    int khB = (lane >> 3) & 1;
    uint32_t aob[4]; int asw[4];
#pragma unroll
    for (int mf = 0; mf < 4; mf++) {
        int r = wm * 64 + mf * 16 + (lane & 7) + 8 * ((lane >> 3) & 1);
        aob[mf] = (uint32_t)r * 128u;
        asw[mf] = r & 7;
    }
    uint32_t bob[4]; int bsw[4];
#pragma unroll
    for (int p = 0; p < 4; p++) {
        int n = wn * 64 + p * 16 + (lane & 7) + 8 * ((lane >> 4) & 1);
        bob[p] = (uint32_t)n * 128u;
        bsw[p] = n & 7;
    }

    float acc[4][8][4];
#pragma unroll
    for (int i = 0; i < 4; i++)
#pragma unroll
        for (int j = 0; j < 8; j++)
#pragma unroll
            for (int q = 0; q < 4; q++) acc[i][j][q] = 0.f;

    // prologue
    load_chunk(0, 0);
    load_chunk(1, 1);

    int slot = 0;
    for (int c = 0; c < CHUNKS; c++) {
        asm volatile("cp.async.wait_group 1;" ::: "memory");
        __syncthreads();
        int nslot = slot + 2; if (nslot >= STAGES) nslot -= STAGES;
        if (c + 2 < CHUNKS) load_chunk(c + 2, nslot);
        else asm volatile("cp.async.commit_group;" ::: "memory");

        uint32_t as = tiles0 + slot * STAGE_BYTES;
        uint32_t bs = as + A_BYTES;
#pragma unroll
        for (int ks = 0; ks < 4; ks++) {
            uint32_t aR[4][4], bR[8][2];
#pragma unroll
            for (int mf = 0; mf < 4; mf++)
                ldsm_x4(aR[mf][0], aR[mf][1], aR[mf][2], aR[mf][3],
                        as + aob[mf] + (uint32_t)(((ks * 2 + khA) ^ asw[mf]) << 4));
#pragma unroll
            for (int p = 0; p < 4; p++)
                ldsm_x4(bR[2 * p][0], bR[2 * p][1], bR[2 * p + 1][0], bR[2 * p + 1][1],
                        bs + bob[p] + (uint32_t)(((ks * 2 + khB) ^ bsw[p]) << 4));
#pragma unroll
            for (int mf = 0; mf < 4; mf++)
#pragma unroll
                for (int nf = 0; nf < 8; nf++)
                    mma_f16(acc[mf][nf], aR[mf], bR[nf]);
        }
        if (++slot == STAGES) slot = 0;
    }

    // epilogue: (acc + bias) * topp, scatter rows to tokens
    int g = lane >> 2, tq = lane & 3;
    const float* brow = bias + (size_t)e * DD + (size_t)ntile * NT;
#pragma unroll
    for (int mf = 0; mf < 4; mf++) {
#pragma unroll
        for (int half = 0; half < 2; half++) {
            int m = mtile * MT + wm * 64 + mf * 16 + g + half * 8;
            int tok = g_row2tok[m];
            if (tok < 0) continue;
            float tp = g_topp[tok];
            float* orow = out + (size_t)tok * DD + (size_t)ntile * NT;
#pragma unroll
            for (int nf = 0; nf < 8; nf++) {
                int n = wn * 64 + nf * 8 + 2 * tq;
                float2 o;
                o.x = (acc[mf][nf][half * 2 + 0] + brow[n]) * tp;
                o.y = (acc[mf][nf][half * 2 + 1] + brow[n + 1]) * tp;
                *(float2*)(orow + n) = o;
            }
        }
    }
}

// ---------------- launcher ----------------
extern "C" void kernel_launch(void* const* d_in, const int* in_sizes, int n_in,
                              void* d_out, int out_size) {
    const float* x  = (const float*)d_in[0];
    const float* Wr = (const float*)d_in[1];
    const float* br = (const float*)d_in[2];
    const float* W  = (const float*)d_in[3];
    const float* b  = (const float*)d_in[4];
    float* out = (float*)d_out;

    cudaFuncSetAttribute(k_gemm, cudaFuncAttributeMaxDynamicSharedMemorySize, SMEM_NEED);

    k_reset<<<(NROWS + 255) / 256, 256>>>();
    k_convw<<<(int)((size_t)EE * DD * DD / 4 / 256), 256>>>((const float4*)W);
    k_router<<<TT / 8, 256>>>(x, Wr, br);
    k_schedule<<<1, 32>>>(out, out_size);
    k_fillmap<<<TT / 256, 256>>>();
    k_gemm<<<dim3(DD / NT, MAX_MTILES), 128, SMEM_NEED>>>(b, out);
}

// round 12
// speedup vs baseline: 3.0861x; 1.0617x over previous
#include <cuda_runtime.h>
#include <cuda_fp16.h>
#include <cstdint>
#include <cstddef>

#define TT 8192
#define DD 2048
#define EE 8
#define NROWS 9216
#define MAX_MTILES 93    /* ceil(8192/96) + 7 */

#define MT 96            /* CTA tile M */
#define NT 128           /* CTA tile N */
#define KC 64            /* K per chunk (row = 128 bytes fp16) */
#define STAGES 3
#define CHUNKS (DD/KC)   /* 32 */
#define A_BYTES (MT*KC*2)             /* 12288 */
#define B_BYTES (NT*KC*2)             /* 16384 */
#define STAGE_BYTES (A_BYTES+B_BYTES) /* 28672 */
#define SMEM_NEED (STAGES*STAGE_BYTES)/* 86016 */

// ---------------- device scratch ----------------
__device__ __align__(16) __half g_xf[(size_t)TT*DD];     /* token-ordered fp16 x */
__device__ __align__(16) __half g_Wf[(size_t)EE*DD*DD];  /* fp16 W */
__device__ int   g_expert[TT];
__device__ float g_topp[TT];
__device__ int   g_row2tok[NROWS];
__device__ int   g_cnt[EE];
__device__ int   g_cursor[EE];
__device__ float g_tpsum[EE];

// ---------------- helpers ----------------
__device__ __forceinline__ uint32_t smem_u32(const void* p) {
    uint32_t a;
    asm("{ .reg .u64 t; cvta.to.shared.u64 t, %1; cvt.u32.u64 %0, t; }" : "=r"(a) : "l"(p));
    return a;
}
__device__ __forceinline__ void cp_async16(uint32_t dst, const void* src) {
    asm volatile("cp.async.cg.shared.global [%0], [%1], 16;" :: "r"(dst), "l"(src) : "memory");
}
// cp.async with runtime src-size (0 => full zero-fill of the 16B)
__device__ __forceinline__ void cp_async16z(uint32_t dst, const void* src, uint32_t srcsz) {
    asm volatile("cp.async.cg.shared.global [%0], [%1], 16, %2;"
                 :: "r"(dst), "l"(src), "r"(srcsz) : "memory");
}
__device__ __forceinline__ uint2 cvt4_h(float4 v) {
    __half2 a = __floats2half2_rn(v.x, v.y);
    __half2 b = __floats2half2_rn(v.z, v.w);
    uint2 r;
    r.x = *(uint32_t*)&a; r.y = *(uint32_t*)&b;
    return r;
}
__device__ __forceinline__ void ldsm_x4(uint32_t& r0, uint32_t& r1, uint32_t& r2, uint32_t& r3,
                                        uint32_t addr) {
    asm volatile("ldmatrix.sync.aligned.m8n8.x4.shared.b16 {%0,%1,%2,%3}, [%4];"
                 : "=r"(r0), "=r"(r1), "=r"(r2), "=r"(r3) : "r"(addr));
}
__device__ __forceinline__ void mma_f16(float* c, const uint32_t* a, const uint32_t* b) {
    asm volatile(
        "mma.sync.aligned.m16n8k16.row.col.f32.f16.f16.f32 "
        "{%0,%1,%2,%3}, {%4,%5,%6,%7}, {%8,%9}, {%0,%1,%2,%3};"
        : "+f"(c[0]), "+f"(c[1]), "+f"(c[2]), "+f"(c[3])
        : "r"(a[0]), "r"(a[1]), "r"(a[2]), "r"(a[3]), "r"(b[0]), "r"(b[1]));
}

// ---------------- small kernels ----------------
__global__ void k_reset() {
    int i = blockIdx.x * 256 + threadIdx.x;
    if (i < NROWS) g_row2tok[i] = -1;
    if (blockIdx.x == 0 && threadIdx.x < EE) {
        g_cnt[threadIdx.x] = 0; g_cursor[threadIdx.x] = 0; g_tpsum[threadIdx.x] = 0.f;
    }
}

// fused: blocks [0,1024) = router (+x fp16 conversion), blocks [1024,...) = W conversion
__global__ void k_convrouter(const float* __restrict__ x, const float* __restrict__ Wr,
                             const float* __restrict__ br, const float4* __restrict__ W4) {
    if (blockIdx.x >= TT / 8) {
        size_t i = (size_t)(blockIdx.x - TT / 8) * 256 + threadIdx.x;
        ((uint2*)g_Wf)[i] = cvt4_h(W4[i]);
        return;
    }
    int t = blockIdx.x * 8 + (threadIdx.x >> 5);
    int lid = threadIdx.x & 31;
    const float4* xr = (const float4*)(x + (size_t)t * DD);
    const float4* wr = (const float4*)Wr;
    uint2* xo = (uint2*)(g_xf + (size_t)t * DD);
    float acc[EE];
#pragma unroll
    for (int e = 0; e < EE; e++) acc[e] = 0.f;
    for (int i = lid; i < DD / 4; i += 32) {
        float4 xv = xr[i];
        xo[i] = cvt4_h(xv);
#pragma unroll
        for (int e = 0; e < EE; e++) {
            float4 w = wr[e * (DD / 4) + i];
            acc[e] += xv.x * w.x + xv.y * w.y + xv.z * w.z + xv.w * w.w;
        }
    }
#pragma unroll
    for (int e = 0; e < EE; e++)
#pragma unroll
        for (int o = 16; o; o >>= 1) acc[e] += __shfl_xor_sync(0xffffffffu, acc[e], o);
    if (lid == 0) {
        float mx = -1e30f; int idx = 0;
#pragma unroll
        for (int e = 0; e < EE; e++) {
            acc[e] += br[e];
            if (acc[e] > mx) { mx = acc[e]; idx = e; }
        }
        float s = 0.f;
#pragma unroll
        for (int e = 0; e < EE; e++) s += expf(acc[e] - mx);
        float tp = 1.f / s;
        g_expert[t] = idx; g_topp[t] = tp;
        atomicAdd(&g_cnt[idx], 1);
        atomicAdd(&g_tpsum[idx], tp);
    }
}

// fillmap: build row2tok via per-thread prefix over g_cnt; thread 0 of block 0 writes loss
__global__ void k_fillmap(float* __restrict__ out, int out_size) {
    int t = blockIdx.x * 256 + threadIdx.x;
    if (t < TT) {
        int e = g_expert[t];
        int base = 0;
#pragma unroll
        for (int i = 0; i < EE; i++)
            if (i < e) base += ((g_cnt[i] + MT - 1) / MT) * MT;
        int r = base + atomicAdd(&g_cursor[e], 1);
        g_row2tok[r] = t;
    }
    if (blockIdx.x == 0 && threadIdx.x == 0) {
        float loss = 0.f;
#pragma unroll
        for (int e = 0; e < EE; e++) {
            float frac = (float)g_cnt[e] / (float)TT;
            float prob = g_tpsum[e] / ((float)TT * (float)TT);
            loss += frac * prob;
        }
        loss *= 3e-06f * (float)EE;
        if (out_size == TT * DD + 1) out[(size_t)TT * DD] = loss;
    }
}

// ---------------- GEMM (HMMA fp16, 96x128 CTA, 4 warps, warp tile 48x64, occ 2) --------
__global__ void __launch_bounds__(128, 2)
k_gemm(const float* __restrict__ bias, float* __restrict__ out) {
    int mtile = blockIdx.y, ntile = blockIdx.x;

    // inline schedule: which expert owns this mtile?
    int e = -1, nt_total = 0;
#pragma unroll
    for (int i = 0; i < EE; i++) {
        int tiles = (g_cnt[i] + MT - 1) / MT;
        if (mtile >= nt_total && mtile < nt_total + tiles) e = i;
        nt_total += tiles;
    }
    if (e < 0) return;

    extern __shared__ char smem[];
    uint32_t tiles0 = smem_u32(smem);

    int tid = threadIdx.x, wid = tid >> 5, lane = tid & 31;
    int wm = wid >> 1, wn = wid & 1;          // 2 x 2 warp grid, warp tile 48x64

    const __half* Bsrc0 = g_Wf + ((size_t)e * DD + (size_t)ntile * NT) * DD;

    // loader: 8 threads per 128B row; A rows lrow+p*16 (p<6), B rows lrow+p*16 (p<8)
    int lrow = tid >> 3, lp = tid & 7;
    const char* Bg = (const char*)Bsrc0 + lp * 16;

    // indirect A row pointers (gather through row2tok, zero-fill pads)
    const char* aptr[6];
    uint32_t asz[6];
#pragma unroll
    for (int p = 0; p < 6; p++) {
        int tok = g_row2tok[mtile * MT + lrow + p * 16];
        asz[p] = (tok >= 0) ? 16u : 0u;
        aptr[p] = (const char*)(g_xf + (size_t)(tok < 0 ? 0 : tok) * DD) + lp * 16;
    }

    auto load_chunk = [&](int c, int slot) {
        uint32_t abase = tiles0 + slot * STAGE_BYTES;
        uint32_t bbase = abase + A_BYTES;
        size_t coff = (size_t)c * (KC * 2);
#pragma unroll
        for (int p = 0; p < 6; p++) {
            int r = lrow + p * 16;
            uint32_t soff = (uint32_t)r * 128u + (uint32_t)((lp ^ (r & 7)) << 4);
            cp_async16z(abase + soff, aptr[p] + coff, asz[p]);
        }
#pragma unroll
        for (int p = 0; p < 8; p++) {
            int r = lrow + p * 16;
            uint32_t soff = (uint32_t)r * 128u + (uint32_t)((lp ^ (r & 7)) << 4);
            cp_async16(bbase + soff, Bg + coff + (size_t)r * (DD * 2));
        }
        asm volatile("cp.async.commit_group;" ::: "memory");
    };

    // ldmatrix address components (constant over chunks)
    int khA = (lane >> 4) & 1;
    int khB = (lane >> 3) & 1;
    uint32_t aob[3]; int asw[3];
#pragma unroll
    for (int mf = 0; mf < 3; mf++) {
        int r = wm * 48 + mf * 16 + (lane & 7) + 8 * ((lane >> 3) & 1);
        aob[mf] = (uint32_t)r * 128u;
        asw[mf] = r & 7;
    }
    uint32_t bob[4]; int bsw[4];
#pragma unroll
    for (int p = 0; p < 4; p++) {
        int n = wn * 64 + p * 16 + (lane & 7) + 8 * ((lane >> 4) & 1);
        bob[p] = (uint32_t)n * 128u;
        bsw[p] = n & 7;
    }

    float acc[3][8][4];
#pragma unroll
    for (int i = 0; i < 3; i++)
#pragma unroll
        for (int j = 0; j < 8; j++)
#pragma unroll
            for (int q = 0; q < 4; q++) acc[i][j][q] = 0.f;

    // prologue
    load_chunk(0, 0);
    load_chunk(1, 1);

    int slot = 0;
    for (int c = 0; c < CHUNKS; c++) {
        asm volatile("cp.async.wait_group 1;" ::: "memory");
        __syncthreads();
        int nslot = slot + 2; if (nslot >= STAGES) nslot -= STAGES;
        if (c + 2 < CHUNKS) load_chunk(c + 2, nslot);
        else asm volatile("cp.async.commit_group;" ::: "memory");

        uint32_t as = tiles0 + slot * STAGE_BYTES;
        uint32_t bs = as + A_BYTES;
#pragma unroll
        for (int ks = 0; ks < 4; ks++) {
            uint32_t aR[3][4], bR[8][2];
#pragma unroll
            for (int mf = 0; mf < 3; mf++)
                ldsm_x4(aR[mf][0], aR[mf][1], aR[mf][2], aR[mf][3],
                        as + aob[mf] + (uint32_t)(((ks * 2 + khA) ^ asw[mf]) << 4));
#pragma unroll
            for (int p = 0; p < 4; p++)
                ldsm_x4(bR[2 * p][0], bR[2 * p][1], bR[2 * p + 1][0], bR[2 * p + 1][1],
                        bs + bob[p] + (uint32_t)(((ks * 2 + khB) ^ bsw[p]) << 4));
#pragma unroll
            for (int mf = 0; mf < 3; mf++)
#pragma unroll
                for (int nf = 0; nf < 8; nf++)
                    mma_f16(acc[mf][nf], aR[mf], bR[nf]);
        }
        if (++slot == STAGES) slot = 0;
    }

    // epilogue: (acc + bias) * topp, scatter rows to tokens
    int g = lane >> 2, tq = lane & 3;
    const float* brow = bias + (size_t)e * DD + (size_t)ntile * NT;
#pragma unroll
    for (int mf = 0; mf < 3; mf++) {
#pragma unroll
        for (int half = 0; half < 2; half++) {
            int m = mtile * MT + wm * 48 + mf * 16 + g + half * 8;
            int tok = g_row2tok[m];
            if (tok < 0) continue;
            float tp = g_topp[tok];
            float* orow = out + (size_t)tok * DD + (size_t)ntile * NT;
#pragma unroll
            for (int nf = 0; nf < 8; nf++) {
                int n = wn * 64 + nf * 8 + 2 * tq;
                float2 o;
                o.x = (acc[mf][nf][half * 2 + 0] + brow[n]) * tp;
                o.y = (acc[mf][nf][half * 2 + 1] + brow[n + 1]) * tp;
                *(float2*)(orow + n) = o;
            }
        }
    }
}

// ---------------- launcher ----------------
extern "C" void kernel_launch(void* const* d_in, const int* in_sizes, int n_in,
                              void* d_out, int out_size) {
    const float* x  = (const float*)d_in[0];
    const float* Wr = (const float*)d_in[1];
    const float* br = (const float*)d_in[2];
    const float* W  = (const float*)d_in[3];
    const float* b  = (const float*)d_in[4];
    float* out = (float*)d_out;

    cudaFuncSetAttribute(k_gemm, cudaFuncAttributeMaxDynamicSharedMemorySize, SMEM_NEED);

    k_reset<<<(NROWS + 255) / 256, 256>>>();
    k_convrouter<<<TT / 8 + (int)((size_t)EE * DD * DD / 4 / 256), 256>>>(
        x, Wr, br, (const float4*)W);
    k_fillmap<<<TT / 256, 256>>>(out, out_size);
    k_gemm<<<dim3(DD / NT, MAX_MTILES), 128, SMEM_NEED>>>(b, out);
}

// round 13
// speedup vs baseline: 3.2381x; 1.0493x over previous
#include <cuda_runtime.h>
#include <cuda_fp16.h>
#include <cstdint>
#include <cstddef>

#define TT 8192
#define DD 2048
#define EE 8
#define NROWS 9216
#define MAX_MTILES 93    /* ceil(8192/96) + 7 */

#define MT 96            /* CTA tile M */
#define NT 128           /* CTA tile N */
#define KC 64            /* K per chunk (row = 128 bytes fp16) */
#define STAGES 4
#define CHUNKS (DD/KC)   /* 32 */
#define A_BYTES (MT*KC*2)             /* 12288 */
#define B_BYTES (NT*KC*2)             /* 16384 */
#define STAGE_BYTES (A_BYTES+B_BYTES) /* 28672 */
#define SMEM_NEED (STAGES*STAGE_BYTES)/* 114688 */

// ---------------- device scratch ----------------
__device__ __align__(16) __half g_xf[(size_t)TT*DD];     /* token-ordered fp16 x */
__device__ __align__(16) __half g_Wf[(size_t)EE*DD*DD];  /* fp16 W */
__device__ int   g_expert[TT];
__device__ float g_topp[TT];
__device__ int   g_row2tok[NROWS];
__device__ int   g_cnt[EE];
__device__ int   g_cursor[EE];
__device__ float g_tpsum[EE];

// ---------------- helpers ----------------
__device__ __forceinline__ uint32_t smem_u32(const void* p) {
    uint32_t a;
    asm("{ .reg .u64 t; cvta.to.shared.u64 t, %1; cvt.u32.u64 %0, t; }" : "=r"(a) : "l"(p));
    return a;
}
__device__ __forceinline__ void cp_async16(uint32_t dst, const void* src) {
    asm volatile("cp.async.cg.shared.global [%0], [%1], 16;" :: "r"(dst), "l"(src) : "memory");
}
// cp.async with runtime src-size (0 => full zero-fill of the 16B)
__device__ __forceinline__ void cp_async16z(uint32_t dst, const void* src, uint32_t srcsz) {
    asm volatile("cp.async.cg.shared.global [%0], [%1], 16, %2;"
                 :: "r"(dst), "l"(src), "r"(srcsz) : "memory");
}
__device__ __forceinline__ uint2 cvt4_h(float4 v) {
    __half2 a = __floats2half2_rn(v.x, v.y);
    __half2 b = __floats2half2_rn(v.z, v.w);
    uint2 r;
    r.x = *(uint32_t*)&a; r.y = *(uint32_t*)&b;
    return r;
}
__device__ __forceinline__ void ldsm_x4(uint32_t& r0, uint32_t& r1, uint32_t& r2, uint32_t& r3,
                                        uint32_t addr) {
    asm volatile("ldmatrix.sync.aligned.m8n8.x4.shared.b16 {%0,%1,%2,%3}, [%4];"
                 : "=r"(r0), "=r"(r1), "=r"(r2), "=r"(r3) : "r"(addr));
}
__device__ __forceinline__ void mma_f16(float* c, const uint32_t* a, const uint32_t* b) {
    asm volatile(
        "mma.sync.aligned.m16n8k16.row.col.f32.f16.f16.f32 "
        "{%0,%1,%2,%3}, {%4,%5,%6,%7}, {%8,%9}, {%0,%1,%2,%3};"
        : "+f"(c[0]), "+f"(c[1]), "+f"(c[2]), "+f"(c[3])
        : "r"(a[0]), "r"(a[1]), "r"(a[2]), "r"(a[3]), "r"(b[0]), "r"(b[1]));
}

// ---------------- small kernels ----------------
__global__ void k_reset() {
    int i = blockIdx.x * 256 + threadIdx.x;
    if (i < NROWS) g_row2tok[i] = -1;
    if (blockIdx.x == 0 && threadIdx.x < EE) {
        g_cnt[threadIdx.x] = 0; g_cursor[threadIdx.x] = 0; g_tpsum[threadIdx.x] = 0.f;
    }
}

// fused: blocks [0,1024) = router (+x fp16 conversion), blocks [1024,...) = W conversion
__global__ void k_convrouter(const float* __restrict__ x, const float* __restrict__ Wr,
                             const float* __restrict__ br, const float4* __restrict__ W4) {
    if (blockIdx.x >= TT / 8) {
        size_t i = (size_t)(blockIdx.x - TT / 8) * 256 + threadIdx.x;
        ((uint2*)g_Wf)[i] = cvt4_h(W4[i]);
        return;
    }
    int t = blockIdx.x * 8 + (threadIdx.x >> 5);
    int lid = threadIdx.x & 31;
    const float4* xr = (const float4*)(x + (size_t)t * DD);
    const float4* wr = (const float4*)Wr;
    uint2* xo = (uint2*)(g_xf + (size_t)t * DD);
    float acc[EE];
#pragma unroll
    for (int e = 0; e < EE; e++) acc[e] = 0.f;
    for (int i = lid; i < DD / 4; i += 32) {
        float4 xv = xr[i];
        xo[i] = cvt4_h(xv);
#pragma unroll
        for (int e = 0; e < EE; e++) {
            float4 w = wr[e * (DD / 4) + i];
            acc[e] += xv.x * w.x + xv.y * w.y + xv.z * w.z + xv.w * w.w;
        }
    }
#pragma unroll
    for (int e = 0; e < EE; e++)
#pragma unroll
        for (int o = 16; o; o >>= 1) acc[e] += __shfl_xor_sync(0xffffffffu, acc[e], o);
    if (lid == 0) {
        float mx = -1e30f; int idx = 0;
#pragma unroll
        for (int e = 0; e < EE; e++) {
            acc[e] += br[e];
            if (acc[e] > mx) { mx = acc[e]; idx = e; }
        }
        float s = 0.f;
#pragma unroll
        for (int e = 0; e < EE; e++) s += expf(acc[e] - mx);
        float tp = 1.f / s;
        g_expert[t] = idx; g_topp[t] = tp;
        atomicAdd(&g_cnt[idx], 1);
        atomicAdd(&g_tpsum[idx], tp);
    }
}

// fillmap: build row2tok via per-thread prefix over g_cnt; thread 0 of block 0 writes loss
__global__ void k_fillmap(float* __restrict__ out, int out_size) {
    int t = blockIdx.x * 256 + threadIdx.x;
    if (t < TT) {
        int e = g_expert[t];
        int base = 0;
#pragma unroll
        for (int i = 0; i < EE; i++)
            if (i < e) base += ((g_cnt[i] + MT - 1) / MT) * MT;
        int r = base + atomicAdd(&g_cursor[e], 1);
        g_row2tok[r] = t;
    }
    if (blockIdx.x == 0 && threadIdx.x == 0) {
        float loss = 0.f;
#pragma unroll
        for (int e = 0; e < EE; e++) {
            float frac = (float)g_cnt[e] / (float)TT;
            float prob = g_tpsum[e] / ((float)TT * (float)TT);
            loss += frac * prob;
        }
        loss *= 3e-06f * (float)EE;
        if (out_size == TT * DD + 1) out[(size_t)TT * DD] = loss;
    }
}

// ------ GEMM (HMMA fp16, 96x128 CTA, 4 warps, warp 48x64, occ 2, ks-pipelined) --------
__global__ void __launch_bounds__(128, 2)
k_gemm(const float* __restrict__ bias, float* __restrict__ out) {
    int mtile = blockIdx.y, ntile = blockIdx.x;

    // inline schedule: which expert owns this mtile?
    int e = -1, nt_total = 0;
#pragma unroll
    for (int i = 0; i < EE; i++) {
        int tiles = (g_cnt[i] + MT - 1) / MT;
        if (mtile >= nt_total && mtile < nt_total + tiles) e = i;
        nt_total += tiles;
    }
    if (e < 0) return;

    extern __shared__ char smem[];
    uint32_t tiles0 = smem_u32(smem);

    int tid = threadIdx.x, wid = tid >> 5, lane = tid & 31;
    int wm = wid >> 1, wn = wid & 1;          // 2 x 2 warp grid, warp tile 48x64

    const __half* Bsrc0 = g_Wf + ((size_t)e * DD + (size_t)ntile * NT) * DD;

    // loader: 8 threads per 128B row
    int lrow = tid >> 3, lp = tid & 7;
    const char* Bg = (const char*)Bsrc0 + lp * 16;

    // indirect A row pointers (gather through row2tok, zero-fill pads)
    const char* aptr[6];
    uint32_t asz[6];
#pragma unroll
    for (int p = 0; p < 6; p++) {
        int tok = g_row2tok[mtile * MT + lrow + p * 16];
        asz[p] = (tok >= 0) ? 16u : 0u;
        aptr[p] = (const char*)(g_xf + (size_t)(tok < 0 ? 0 : tok) * DD) + lp * 16;
    }

    auto load_chunk = [&](int c, int slot) {
        uint32_t abase = tiles0 + slot * STAGE_BYTES;
        uint32_t bbase = abase + A_BYTES;
        size_t coff = (size_t)c * (KC * 2);
#pragma unroll
        for (int p = 0; p < 6; p++) {
            int r = lrow + p * 16;
            uint32_t soff = (uint32_t)r * 128u + (uint32_t)((lp ^ (r & 7)) << 4);
            cp_async16z(abase + soff, aptr[p] + coff, asz[p]);
        }
#pragma unroll
        for (int p = 0; p < 8; p++) {
            int r = lrow + p * 16;
            uint32_t soff = (uint32_t)r * 128u + (uint32_t)((lp ^ (r & 7)) << 4);
            cp_async16(bbase + soff, Bg + coff + (size_t)r * (DD * 2));
        }
        asm volatile("cp.async.commit_group;" ::: "memory");
    };

    // ldmatrix address components (constant over chunks)
    int khA = (lane >> 4) & 1;
    int khB = (lane >> 3) & 1;
    uint32_t aob[3]; int asw[3];
#pragma unroll
    for (int mf = 0; mf < 3; mf++) {
        int r = wm * 48 + mf * 16 + (lane & 7) + 8 * ((lane >> 3) & 1);
        aob[mf] = (uint32_t)r * 128u;
        asw[mf] = r & 7;
    }
    uint32_t bob[4]; int bsw[4];
#pragma unroll
    for (int p = 0; p < 4; p++) {
        int n = wn * 64 + p * 16 + (lane & 7) + 8 * ((lane >> 4) & 1);
        bob[p] = (uint32_t)n * 128u;
        bsw[p] = n & 7;
    }

    float acc[3][8][4];
#pragma unroll
    for (int i = 0; i < 3; i++)
#pragma unroll
        for (int j = 0; j < 8; j++)
#pragma unroll
            for (int q = 0; q < 4; q++) acc[i][j][q] = 0.f;

    // fragment double buffers
    uint32_t aF[2][3][4], bF[2][8][2];

    auto ld_frags = [&](uint32_t as, uint32_t bs, int ks, int buf) {
#pragma unroll
        for (int mf = 0; mf < 3; mf++)
            ldsm_x4(aF[buf][mf][0], aF[buf][mf][1], aF[buf][mf][2], aF[buf][mf][3],
                    as + aob[mf] + (uint32_t)(((ks * 2 + khA) ^ asw[mf]) << 4));
#pragma unroll
        for (int p = 0; p < 4; p++)
            ldsm_x4(bF[buf][2 * p][0], bF[buf][2 * p][1],
                    bF[buf][2 * p + 1][0], bF[buf][2 * p + 1][1],
                    bs + bob[p] + (uint32_t)(((ks * 2 + khB) ^ bsw[p]) << 4));
    };

    // prologue: fill 3 stages
    load_chunk(0, 0);
    load_chunk(1, 1);
    load_chunk(2, 2);

    int slot = 0;
    for (int c = 0; c < CHUNKS; c++) {
        asm volatile("cp.async.wait_group 2;" ::: "memory");
        __syncthreads();

        uint32_t as = tiles0 + slot * STAGE_BYTES;
        uint32_t bs = as + A_BYTES;
        ld_frags(as, bs, 0, 0);                 // start MMA critical path first

        int nslot = slot + 3; if (nslot >= STAGES) nslot -= STAGES;
        if (c + 3 < CHUNKS) load_chunk(c + 3, nslot);
        else asm volatile("cp.async.commit_group;" ::: "memory");

#pragma unroll
        for (int ks = 0; ks < 4; ks++) {
            int cb = ks & 1;
            if (ks < 3) ld_frags(as, bs, ks + 1, cb ^ 1);
#pragma unroll
            for (int mf = 0; mf < 3; mf++)
#pragma unroll
                for (int nf = 0; nf < 8; nf++)
                    mma_f16(acc[mf][nf], aF[cb][mf], bF[cb][nf]);
        }
        if (++slot == STAGES) slot = 0;
    }

    // epilogue: (acc + bias) * topp, scatter rows to tokens
    int g = lane >> 2, tq = lane & 3;
    const float* brow = bias + (size_t)e * DD + (size_t)ntile * NT;
#pragma unroll
    for (int mf = 0; mf < 3; mf++) {
#pragma unroll
        for (int half = 0; half < 2; half++) {
            int m = mtile * MT + wm * 48 + mf * 16 + g + half * 8;
            int tok = g_row2tok[m];
            if (tok < 0) continue;
            float tp = g_topp[tok];
            float* orow = out + (size_t)tok * DD + (size_t)ntile * NT;
#pragma unroll
            for (int nf = 0; nf < 8; nf++) {
                int n = wn * 64 + nf * 8 + 2 * tq;
                float2 o;
                o.x = (acc[mf][nf][half * 2 + 0] + brow[n]) * tp;
                o.y = (acc[mf][nf][half * 2 + 1] + brow[n + 1]) * tp;
                *(float2*)(orow + n) = o;
            }
        }
    }
}

// ---------------- launcher ----------------
extern "C" void kernel_launch(void* const* d_in, const int* in_sizes, int n_in,
                              void* d_out, int out_size) {
    const float* x  = (const float*)d_in[0];
    const float* Wr = (const float*)d_in[1];
    const float* br = (const float*)d_in[2];
    const float* W  = (const float*)d_in[3];
    const float* b  = (const float*)d_in[4];
    float* out = (float*)d_out;

    cudaFuncSetAttribute(k_gemm, cudaFuncAttributeMaxDynamicSharedMemorySize, SMEM_NEED);

    k_reset<<<(NROWS + 255) / 256, 256>>>();
    k_convrouter<<<TT / 8 + (int)((size_t)EE * DD * DD / 4 / 256), 256>>>(
        x, Wr, br, (const float4*)W);
    k_fillmap<<<TT / 256, 256>>>(out, out_size);
    k_gemm<<<dim3(DD / NT, MAX_MTILES), 128, SMEM_NEED>>>(b, out);
}